// round 5
// baseline (speedup 1.0000x reference)
#include <cuda_runtime.h>
#include <cuda_bf16.h>

#define NN  131072
#define CC  128
#define SS  6
#define BB  6
#define EE  131072
#define ELE 32768
#define GN_EPS 1e-5f

// ---------------- device scratch ----------------
static __device__ float g_bufA[(size_t)NN * CC];
static __device__ float g_bufB[(size_t)NN * CC];
static __device__ float g_temp[(size_t)NN * CC];
// split planes: [N][64] u32 (bf16x2 pairs), hi then lo
static __device__ unsigned g_fhi[(size_t)NN * 64];
static __device__ unsigned g_flo[(size_t)NN * 64];
static __device__ unsigned g_hhi[(size_t)NN * 64];
static __device__ unsigned g_hlo[(size_t)NN * 64];
// split weights: [96][hi 8192 | lo 8192] u32, layout [n=128][kp=64]
static __device__ unsigned g_wsp[(size_t)96 * 16384];

// ---------------- bf16 split helpers ----------------
__device__ __forceinline__ unsigned pack_bf2(__nv_bfloat16 lo16, __nv_bfloat16 hi16) {
    __nv_bfloat162 t(lo16, hi16);
    return *reinterpret_cast<unsigned*>(&t);
}
__device__ __forceinline__ void bsplit(float x, __nv_bfloat16& h, __nv_bfloat16& l) {
    h = __float2bfloat16(x);
    l = __float2bfloat16(x - __bfloat162float(h));
}
__device__ __forceinline__ void split2(float a, float b, unsigned& hi, unsigned& lo) {
    __nv_bfloat16 h0, l0, h1, l1;
    bsplit(a, h0, l0); bsplit(b, h1, l1);
    hi = pack_bf2(h0, h1);
    lo = pack_bf2(l0, l1);
}

__device__ __forceinline__ void mma16816(float acc[4],
                                         unsigned a0, unsigned a1, unsigned a2, unsigned a3,
                                         unsigned b0, unsigned b1) {
    asm volatile(
        "mma.sync.aligned.m16n8k16.row.col.f32.bf16.bf16.f32 "
        "{%0,%1,%2,%3}, {%4,%5,%6,%7}, {%8,%9}, {%0,%1,%2,%3};"
        : "+f"(acc[0]), "+f"(acc[1]), "+f"(acc[2]), "+f"(acc[3])
        : "r"(a0), "r"(a1), "r"(a2), "r"(a3), "r"(b0), "r"(b1));
}
__device__ __forceinline__ void ldsm_x4(unsigned& r0, unsigned& r1, unsigned& r2, unsigned& r3,
                                        unsigned addr) {
    asm volatile("ldmatrix.sync.aligned.m8n8.x4.shared.b16 {%0,%1,%2,%3}, [%4];"
                 : "=r"(r0), "=r"(r1), "=r"(r2), "=r"(r3) : "r"(addr));
}
__device__ __forceinline__ void cp16(unsigned dst_sh, const void* src) {
    asm volatile("cp.async.cg.shared.global [%0], [%1], 16;" :: "r"(dst_sh), "l"(src));
}

// ---------------- weight pre-split kernel ----------------
__global__ void split_w_kernel(const float* __restrict__ ctr_w, const float* __restrict__ pre_w,
                               const float* __restrict__ suc_w, const float* __restrict__ left_w,
                               const float* __restrict__ right_w, const float* __restrict__ ctr2_w,
                               unsigned* __restrict__ out)
{
    const int m = blockIdx.x;
    const float* W;
    if (m < 6)       W = ctr_w   + (size_t)m        * 16384;
    else if (m < 42) W = pre_w   + (size_t)(m - 6)  * 16384;
    else if (m < 78) W = suc_w   + (size_t)(m - 42) * 16384;
    else if (m < 84) W = left_w  + (size_t)(m - 78) * 16384;
    else if (m < 90) W = right_w + (size_t)(m - 84) * 16384;
    else             W = ctr2_w  + (size_t)(m - 90) * 16384;
    unsigned* hi = out + (size_t)m * 16384;
    unsigned* lo = hi + 8192;
#pragma unroll
    for (int i = 0; i < 32; i++) {
        int p  = threadIdx.x + i * 256;
        int n  = p & 127;
        int kp = p >> 7;
        float w0 = W[(2 * kp) * CC + n];
        float w1 = W[(2 * kp + 1) * CC + n];
        unsigned h, l;
        split2(w0, w1, h, l);
        hi[n * 64 + kp] = h;
        lo[n * 64 + kp] = l;
    }
}

// ---------------- pipelined gather-MMA-scatter / dense GEMM ----------------
// Tile: 256 rows x 128 cols. 512 threads = 16 warps as 4 row-groups (64 rows) x 4 col-groups (32 cols).
// smem (u32 units):
//   sW     [0,     16384): plane*8192 + n*64 + chunk swz (c^(n&7), 16 chunks/row)
//   sA     [16384, 49152): kc-stage*16384 + plane*8192 + r*32 + chunk swz (c^(r&7), 8 chunks/row)
//   sIdx   [49152, 50176): slot*512 + {u:0-255, v:256-511}
#define SMEM_U32 50176
#define SMEM_BYTES (SMEM_U32 * 4)

template <bool SCATTER>
__device__ __forceinline__ void stage_chunk(unsigned shb, int kc,
                                            const uint4* __restrict__ Ahi,
                                            const uint4* __restrict__ Alo,
                                            const int* sV, int row0, int tid)
{
    const unsigned dstbase = shb + ((16384u + (unsigned)kc * 16384u) << 2);
#pragma unroll
    for (int j = 0; j < 8; j++) {
        int fi = tid + j * 512;          // 0..4095
        int plane = fi >> 11;
        int p = fi & 2047;
        int r = p >> 3;
        int c = p & 7;
        int src_row = SCATTER ? sV[r] : (row0 + r);
        const uint4* src = (plane ? Alo : Ahi) + (size_t)src_row * 16 + kc * 8 + c;
        unsigned dst = dstbase + ((unsigned)(plane * 8192 + r * 32 + ((c ^ (r & 7)) << 2)) << 2);
        cp16(dst, src);
    }
}

template <bool SCATTER>
__global__ void __launch_bounds__(512, 1)
msg_mma_kernel(const uint4* __restrict__ Ahi,    // [N][16] uint4
               const uint4* __restrict__ Alo,
               const unsigned* __restrict__ Wsp,  // + blockIdx.y*16384
               const int* __restrict__ u_idx,     // + blockIdx.y*n_rows
               const int* __restrict__ v_idx,
               float* __restrict__ out,
               int n_rows)
{
    extern __shared__ unsigned smem_u[];
    int* sIdx = (int*)(smem_u + 49152);

    const int tid  = threadIdx.x;
    const int lane = tid & 31;
    const int wid  = tid >> 5;
    const int wr   = wid & 3;        // 64-row group
    const int wc   = wid >> 2;       // 32-col group
    const int tig  = lane & 3;
    const int gid  = lane >> 2;

    const int n_tiles = n_rows >> 8;
    int tile = blockIdx.x;
    if (tile >= n_tiles) return;

    const unsigned shb = (unsigned)__cvta_generic_to_shared((void*)smem_u);

    // ---- stage W (once, swizzled) ----
    {
        const uint4* wg = (const uint4*)(Wsp + (size_t)blockIdx.y * 16384);
#pragma unroll
        for (int j = 0; j < 8; j++) {
            int fi = tid + j * 512;      // 0..4095
            int plane = fi >> 11;
            int p = fi & 2047;
            int n = p >> 4;
            int c = p & 15;
            uint4 v = wg[fi];
            *(uint4*)(smem_u + plane * 8192 + n * 64 + ((c ^ (n & 7)) << 2)) = v;
        }
    }

    // ---- prologue: idx for first tile, then stage both k-chunks ----
    if (SCATTER) {
        const int* src = (tid < 256) ? u_idx : v_idx;
        sIdx[tid] = src[(size_t)blockIdx.y * n_rows + (tile << 8) + (tid & 255)];
    }
    __syncthreads();
    stage_chunk<SCATTER>(shb, 0, Ahi, Alo, sIdx + 256, tile << 8, tid);
    asm volatile("cp.async.commit_group;" ::: "memory");
    stage_chunk<SCATTER>(shb, 1, Ahi, Alo, sIdx + 256, tile << 8, tid);
    asm volatile("cp.async.commit_group;" ::: "memory");

    // ---- fragment addressing ----
    const int hi4A = lane >> 4;
    const int hi4B = (lane & 8) >> 3;
    unsigned aOff[4][2];
    int swzA[4];
#pragma unroll
    for (int rt = 0; rt < 4; rt++) {
        int rr = wr * 64 + rt * 16 + (lane & 15);
        swzA[rt] = rr & 7;
#pragma unroll
        for (int pl = 0; pl < 2; pl++)
            aOff[rt][pl] = (unsigned)((pl * 8192 + rr * 32) << 2);
    }
    unsigned bBase[2][2];
    int swzB[2];
#pragma unroll
    for (int nt2 = 0; nt2 < 2; nt2++) {
        int nn = wc * 32 + nt2 * 16 + (lane & 7) + ((lane & 16) >> 1);
        swzB[nt2] = nn & 7;
#pragma unroll
        for (int pl = 0; pl < 2; pl++)
            bBase[nt2][pl] = shb + ((unsigned)(pl * 8192 + nn * 64) << 2);
    }

#define COMPUTE_CHUNK(kc)                                                                   \
    do {                                                                                    \
        const unsigned stb = shb + ((16384u + (kc) * 16384u) << 2);                         \
        _Pragma("unroll")                                                                   \
        for (int ksl = 0; ksl < 4; ksl++) {                                                 \
            unsigned bh[2][4], bl[2][4];                                                    \
            _Pragma("unroll")                                                               \
            for (int nt2 = 0; nt2 < 2; nt2++) {                                             \
                unsigned ch = (unsigned)(((2 * ((kc) * 4 + ksl) + hi4B) ^ swzB[nt2]) << 4); \
                ldsm_x4(bh[nt2][0], bh[nt2][1], bh[nt2][2], bh[nt2][3], bBase[nt2][0] + ch);\
                ldsm_x4(bl[nt2][0], bl[nt2][1], bl[nt2][2], bl[nt2][3], bBase[nt2][1] + ch);\
            }                                                                               \
            _Pragma("unroll")                                                               \
            for (int rt = 0; rt < 4; rt++) {                                                \
                unsigned ah[4], al[4];                                                      \
                unsigned ca = (unsigned)(((2 * ksl + hi4A) ^ swzA[rt]) << 4);               \
                ldsm_x4(ah[0], ah[1], ah[2], ah[3], stb + aOff[rt][0] + ca);                \
                ldsm_x4(al[0], al[1], al[2], al[3], stb + aOff[rt][1] + ca);                \
                _Pragma("unroll")                                                           \
                for (int nt2 = 0; nt2 < 2; nt2++) {                                         \
                    _Pragma("unroll")                                                       \
                    for (int half = 0; half < 2; half++) {                                  \
                        const int nt = nt2 * 2 + half;                                      \
                        unsigned b0h = bh[nt2][2 * half], b1h = bh[nt2][2 * half + 1];      \
                        unsigned b0l = bl[nt2][2 * half], b1l = bl[nt2][2 * half + 1];      \
                        mma16816(acc[rt][nt], ah[0], ah[1], ah[2], ah[3], b0h, b1h);        \
                        mma16816(acc[rt][nt], ah[0], ah[1], ah[2], ah[3], b0l, b1l);        \
                        mma16816(acc[rt][nt], al[0], al[1], al[2], al[3], b0h, b1h);        \
                    }                                                                       \
                }                                                                           \
            }                                                                               \
        }                                                                                   \
    } while (0)

    int slot = 0;
#pragma unroll 1
    while (true) {
        const int row0 = tile << 8;
        const int next = tile + gridDim.x;
        const bool has_next = (next < n_tiles);

        int nreg = 0;
        if (SCATTER && has_next) {
            const int* src = (tid < 256) ? u_idx : v_idx;
            nreg = src[(size_t)blockIdx.y * n_rows + (next << 8) + (tid & 255)];
        }

        float acc[4][4][4];
#pragma unroll
        for (int rt = 0; rt < 4; rt++)
#pragma unroll
            for (int nt = 0; nt < 4; nt++)
#pragma unroll
                for (int q = 0; q < 4; q++) acc[rt][nt][q] = 0.f;

        asm volatile("cp.async.wait_group 1;" ::: "memory");
        __syncthreads();                 // k0 chunk visible
        COMPUTE_CHUNK(0);

        asm volatile("cp.async.wait_group 0;" ::: "memory");
        if (SCATTER && has_next) sIdx[(slot ^ 1) * 512 + tid] = nreg;
        __syncthreads();                 // k1 visible; k0 slot free; next idx visible
        if (has_next) {
            stage_chunk<SCATTER>(shb, 0, Ahi, Alo, sIdx + (slot ^ 1) * 512 + 256,
                                 next << 8, tid);
            asm volatile("cp.async.commit_group;" ::: "memory");
        }
        COMPUTE_CHUNK(1);

        // ---- epilogue ----
        const bool even = (tig & 1) == 0;
        const int colofs = (tig & 2) ? 4 : 0;
#pragma unroll
        for (int rt = 0; rt < 4; rt++) {
            const int arow = wr * 64 + rt * 16 + gid + (even ? 0 : 8);
            float* base;
            if (SCATTER) base = out + (size_t)sIdx[slot * 512 + arow] * CC;
            else         base = out + (size_t)(row0 + arow) * CC;
#pragma unroll
            for (int nt = 0; nt < 4; nt++) {
                float c0 = acc[rt][nt][0], c1 = acc[rt][nt][1];
                float c2 = acc[rt][nt][2], c3 = acc[rt][nt][3];
                float e0 = __shfl_xor_sync(0xffffffffu, c0, 1);
                float e1 = __shfl_xor_sync(0xffffffffu, c1, 1);
                float e2 = __shfl_xor_sync(0xffffffffu, c2, 1);
                float e3 = __shfl_xor_sync(0xffffffffu, c3, 1);
                float x0, x1, x2, x3;
                if (even) { x0 = c0; x1 = c1; x2 = e0; x3 = e1; }
                else      { x0 = e2; x1 = e3; x2 = c2; x3 = c3; }
                float* p = base + wc * 32 + nt * 8 + colofs;
                if (SCATTER) {
                    asm volatile("red.global.add.v4.f32 [%0], {%1,%2,%3,%4};"
                                 :: "l"(p), "f"(x0), "f"(x1), "f"(x2), "f"(x3) : "memory");
                } else {
                    float4 v; v.x = x0; v.y = x1; v.z = x2; v.w = x3;
                    *(float4*)p = v;
                }
            }
        }

        if (!has_next) break;
        __syncthreads();                 // k1 slot free; tile-t idx free
        stage_chunk<SCATTER>(shb, 1, Ahi, Alo, sIdx + (slot ^ 1) * 512 + 256,
                             next << 8, tid);
        asm volatile("cp.async.commit_group;" ::: "memory");
        tile = next;
        slot ^= 1;
    }
#undef COMPUTE_CHUNK
}

// ---------------- input encoder (+ split write) ----------------
__global__ void encoder_kernel(const float* __restrict__ ctrs, const float* __restrict__ feats,
                               const float* __restrict__ icw0, const float* __restrict__ icb0,
                               const float* __restrict__ icw1, const float* __restrict__ icg,
                               const float* __restrict__ icbt,
                               const float* __restrict__ ifw0, const float* __restrict__ ifb0,
                               const float* __restrict__ ifw1, const float* __restrict__ ifg,
                               const float* __restrict__ ifbt,
                               float* __restrict__ out,
                               unsigned* __restrict__ ohi, unsigned* __restrict__ olo)
{
    const int tid = threadIdx.x;
    const int r = tid >> 7;
    const int c = tid & 127;
    const int row = (blockIdx.x << 1) + r;
    const int warp = (tid >> 5) & 3;
    const int lane = tid & 31;
    __shared__ float sh[2][CC];
    __shared__ float sred[2][2][4];

    float ysum = 0.f;
#pragma unroll
    for (int br = 0; br < 2; br++) {
        const float* x  = br ? feats : ctrs;
        const float* w0 = br ? ifw0 : icw0;
        const float* b0 = br ? ifb0 : icb0;
        const float* w1 = br ? ifw1 : icw1;
        const float* g  = br ? ifg  : icg;
        const float* bt = br ? ifbt : icbt;
        const float x0 = x[row * 2 + 0];
        const float x1 = x[row * 2 + 1];
        float h = fmaxf(fmaf(x1, w0[CC + c], fmaf(x0, w0[c], b0[c])), 0.f);
        __syncthreads();
        sh[r][c] = h;
        __syncthreads();
        float z = 0.f;
#pragma unroll 8
        for (int k = 0; k < CC; k++) z = fmaf(sh[r][k], w1[k * CC + c], z);
        float s = z, sq = z * z;
#pragma unroll
        for (int o = 16; o > 0; o >>= 1) {
            s  += __shfl_xor_sync(0xffffffffu, s, o);
            sq += __shfl_xor_sync(0xffffffffu, sq, o);
        }
        if (lane == 0) { sred[r][0][warp] = s; sred[r][1][warp] = sq; }
        __syncthreads();
        float mu  = (sred[r][0][0] + sred[r][0][1] + sred[r][0][2] + sred[r][0][3]) * (1.f / CC);
        float ms  = (sred[r][1][0] + sred[r][1][1] + sred[r][1][2] + sred[r][1][3]) * (1.f / CC);
        float var = ms - mu * mu;
        ysum += (z - mu) * rsqrtf(var + GN_EPS) * g[c] + bt[c];
    }
    float y = fmaxf(ysum, 0.f);
    out[(size_t)row * CC + c] = y;
    float yn = __shfl_down_sync(0xffffffffu, y, 1);
    if ((c & 1) == 0) {
        unsigned h, l; split2(y, yn, h, l);
        ohi[(size_t)row * 64 + (c >> 1)] = h;
        olo[(size_t)row * 64 + (c >> 1)] = l;
    }
}

// ---------------- GN + relu -> split planes only ----------------
__global__ void norm_relu_kernel(const float* __restrict__ in,
                                 const float* __restrict__ g, const float* __restrict__ b,
                                 unsigned* __restrict__ ohi, unsigned* __restrict__ olo)
{
    const int tid = threadIdx.x;
    const int r = tid >> 7, c = tid & 127;
    const size_t row = (size_t)(blockIdx.x << 1) + r;
    const int warp = (tid >> 5) & 3, lane = tid & 31;
    __shared__ float sred[2][2][4];
    float z = in[row * CC + c];
    float s = z, sq = z * z;
#pragma unroll
    for (int o = 16; o > 0; o >>= 1) {
        s  += __shfl_xor_sync(0xffffffffu, s, o);
        sq += __shfl_xor_sync(0xffffffffu, sq, o);
    }
    if (lane == 0) { sred[r][0][warp] = s; sred[r][1][warp] = sq; }
    __syncthreads();
    float mu  = (sred[r][0][0] + sred[r][0][1] + sred[r][0][2] + sred[r][0][3]) * (1.f / CC);
    float ms  = (sred[r][1][0] + sred[r][1][1] + sred[r][1][2] + sred[r][1][3]) * (1.f / CC);
    float var = ms - mu * mu;
    float y = fmaxf((z - mu) * rsqrtf(var + GN_EPS) * g[c] + b[c], 0.f);
    float yn = __shfl_down_sync(0xffffffffu, y, 1);
    if ((c & 1) == 0) {
        unsigned h, l; split2(y, yn, h, l);
        ohi[row * 64 + (c >> 1)] = h;
        olo[row * 64 + (c >> 1)] = l;
    }
}

// ---------------- GN + residual + relu -> f32 + split planes ----------------
__global__ void norm_res_kernel(const float* __restrict__ in,
                                const float* __restrict__ g, const float* __restrict__ b,
                                const float* __restrict__ iden, float* __restrict__ out,
                                unsigned* __restrict__ ohi, unsigned* __restrict__ olo)
{
    const int tid = threadIdx.x;
    const int r = tid >> 7, c = tid & 127;
    const size_t row = (size_t)(blockIdx.x << 1) + r;
    const int warp = (tid >> 5) & 3, lane = tid & 31;
    __shared__ float sred[2][2][4];
    float z = in[row * CC + c];
    float s = z, sq = z * z;
#pragma unroll
    for (int o = 16; o > 0; o >>= 1) {
        s  += __shfl_xor_sync(0xffffffffu, s, o);
        sq += __shfl_xor_sync(0xffffffffu, sq, o);
    }
    if (lane == 0) { sred[r][0][warp] = s; sred[r][1][warp] = sq; }
    __syncthreads();
    float mu  = (sred[r][0][0] + sred[r][0][1] + sred[r][0][2] + sred[r][0][3]) * (1.f / CC);
    float ms  = (sred[r][1][0] + sred[r][1][1] + sred[r][1][2] + sred[r][1][3]) * (1.f / CC);
    float var = ms - mu * mu;
    float y = (z - mu) * rsqrtf(var + GN_EPS) * g[c] + b[c];
    y = fmaxf(y + iden[row * CC + c], 0.f);
    out[row * CC + c] = y;
    float yn = __shfl_down_sync(0xffffffffu, y, 1);
    if ((c & 1) == 0) {
        unsigned h, l; split2(y, yn, h, l);
        ohi[row * 64 + (c >> 1)] = h;
        olo[row * 64 + (c >> 1)] = l;
    }
}

extern "C" void kernel_launch(void* const* d_in, const int* in_sizes, int n_in,
                              void* d_out, int out_size)
{
    const float* ctrs    = (const float*)d_in[0];
    const float* feats   = (const float*)d_in[1];
    const int*   pre_u   = (const int*)d_in[2];
    const int*   pre_v   = (const int*)d_in[3];
    const int*   suc_u   = (const int*)d_in[4];
    const int*   suc_v   = (const int*)d_in[5];
    const int*   left_u  = (const int*)d_in[6];
    const int*   left_v  = (const int*)d_in[7];
    const int*   right_u = (const int*)d_in[8];
    const int*   right_v = (const int*)d_in[9];
    const float* ic_w0   = (const float*)d_in[10];
    const float* ic_b0   = (const float*)d_in[11];
    const float* ic_w1   = (const float*)d_in[12];
    const float* ic_g    = (const float*)d_in[13];
    const float* ic_bt   = (const float*)d_in[14];
    const float* if_w0   = (const float*)d_in[15];
    const float* if_b0   = (const float*)d_in[16];
    const float* if_w1   = (const float*)d_in[17];
    const float* if_g    = (const float*)d_in[18];
    const float* if_bt   = (const float*)d_in[19];
    const float* ctr_w   = (const float*)d_in[20];
    const float* pre_w   = (const float*)d_in[21];
    const float* suc_w   = (const float*)d_in[22];
    const float* left_w  = (const float*)d_in[23];
    const float* right_w = (const float*)d_in[24];
    const float* norm_g  = (const float*)d_in[25];
    const float* norm_b  = (const float*)d_in[26];
    const float* ctr2_w  = (const float*)d_in[27];
    const float* ctr2_g  = (const float*)d_in[28];
    const float* ctr2_b  = (const float*)d_in[29];

    float *bufA, *bufB, *temp;
    unsigned *fhi, *flo, *hhi, *hlo, *wsp;
    cudaGetSymbolAddress((void**)&bufA, g_bufA);
    cudaGetSymbolAddress((void**)&bufB, g_bufB);
    cudaGetSymbolAddress((void**)&temp, g_temp);
    cudaGetSymbolAddress((void**)&fhi, g_fhi);
    cudaGetSymbolAddress((void**)&flo, g_flo);
    cudaGetSymbolAddress((void**)&hhi, g_hhi);
    cudaGetSymbolAddress((void**)&hlo, g_hlo);
    cudaGetSymbolAddress((void**)&wsp, g_wsp);

    cudaFuncSetAttribute(msg_mma_kernel<false>, cudaFuncAttributeMaxDynamicSharedMemorySize, SMEM_BYTES);
    cudaFuncSetAttribute(msg_mma_kernel<true>,  cudaFuncAttributeMaxDynamicSharedMemorySize, SMEM_BYTES);

    // one-time weight split (96 matrices)
    split_w_kernel<<<96, 256>>>(ctr_w, pre_w, suc_w, left_w, right_w, ctr2_w, wsp);

    // initial feat -> bufA (f32) + split planes
    encoder_kernel<<<NN / 2, 256>>>(ctrs, feats,
                                    ic_w0, ic_b0, ic_w1, ic_g, ic_bt,
                                    if_w0, if_b0, if_w1, if_g, if_bt,
                                    bufA, fhi, flo);

    const uint4* fhi4 = (const uint4*)fhi;
    const uint4* flo4 = (const uint4*)flo;
    const uint4* hhi4 = (const uint4*)hhi;
    const uint4* hlo4 = (const uint4*)hlo;

    float* fin = bufA;
    for (int i = 0; i < BB; i++) {
        // temp = feat @ ctr_w[i]   (512 tiles, 128 CTAs x 4 tiles)
        msg_mma_kernel<false><<<dim3(128, 1), 512, SMEM_BYTES>>>(
            fhi4, flo4, wsp + (size_t)i * 16384, nullptr, nullptr, temp, NN);
        // scatter-add message passes (512 tiles/slice, 74 CTAs stride)
        msg_mma_kernel<true><<<dim3(74, SS), 512, SMEM_BYTES>>>(
            fhi4, flo4, wsp + (size_t)(6 + i * 6) * 16384, pre_u, pre_v, temp, EE);
        msg_mma_kernel<true><<<dim3(74, SS), 512, SMEM_BYTES>>>(
            fhi4, flo4, wsp + (size_t)(42 + i * 6) * 16384, suc_u, suc_v, temp, EE);
        msg_mma_kernel<true><<<dim3(128, 1), 512, SMEM_BYTES>>>(
            fhi4, flo4, wsp + (size_t)(78 + i) * 16384, left_u, left_v, temp, ELE);
        msg_mma_kernel<true><<<dim3(128, 1), 512, SMEM_BYTES>>>(
            fhi4, flo4, wsp + (size_t)(84 + i) * 16384, right_u, right_v, temp, ELE);
        // h = relu(GN(temp)) -> split planes
        norm_relu_kernel<<<NN / 2, 256>>>(temp, norm_g + i * CC, norm_b + i * CC, hhi, hlo);
        // temp = h @ ctr2_w[i]
        msg_mma_kernel<false><<<dim3(128, 1), 512, SMEM_BYTES>>>(
            hhi4, hlo4, wsp + (size_t)(90 + i) * 16384, nullptr, nullptr, temp, NN);
        // feat = relu(GN(temp) + identity)
        float* dst = (i == BB - 1) ? (float*)d_out : ((fin == bufA) ? bufB : bufA);
        norm_res_kernel<<<NN / 2, 256>>>(temp, ctr2_g + i * CC, ctr2_b + i * CC, fin, dst, fhi, flo);
        fin = dst;
    }
}